// round 6
// baseline (speedup 1.0000x reference)
#include <cuda_runtime.h>
#include <math.h>

#define NN 320
#define HN 160
#define NPIX (NN*NN)
#define NVEC (4*NPIX)
#define RHO_F 0.1f
#define EPS_F 1e-12f
#define LS 338

__device__ float2 d_scr[64*NPIX];
__device__ float2 d_x[NVEC];
__device__ float2 d_r[NVEC];
__device__ float2 d_p[NVEC];
__device__ float2 d_Ap[NVEC];
__device__ float2 d_W[NN];
__device__ float  d_maskPT[4*NPIX];   // [s][w_slot][h_slot], rot+perm+scale folded
__device__ float  d_partP[1280];
__device__ float  d_pr[1600];
__device__ float  d_sc[4];

__device__ __forceinline__ float2 cad(float2 a, float2 b){ return make_float2(a.x+b.x, a.y+b.y); }
__device__ __forceinline__ float2 csb(float2 a, float2 b){ return make_float2(a.x-b.x, a.y-b.y); }
__device__ __forceinline__ float2 cml(float2 a, float2 b){
    return make_float2(fmaf(a.x,b.x,-a.y*b.y), fmaf(a.x,b.y, a.y*b.x));
}
__device__ __forceinline__ float2 cmlcj(float2 a, float2 b){
    return make_float2(fmaf(a.x,b.x, a.y*b.y), fmaf(a.y,b.x,-a.x*b.y));
}
template<int DIR>
__device__ __forceinline__ float2 tw(const float2* W, int idx){
    float2 w = W[idx];
    return (DIR > 0) ? w : make_float2(w.x, -w.y);
}
__device__ __forceinline__ int rot160(int j){ return (j < HN) ? j + HN : j - HN; }
// slot s holds DFT frequency Pmap(s)
__device__ __forceinline__ int Pmap(int s){
    int t = s % 80;
    return 4*(t%20) + t/20 + 80*(s/80);
}

template<int DIR>
__device__ __forceinline__ void r4b(float2 x[4]){
    float2 t0 = cad(x[0],x[2]), t1 = csb(x[0],x[2]);
    float2 t2 = cad(x[1],x[3]), t3 = csb(x[1],x[3]);
    x[0] = cad(t0,t2); x[2] = csb(t0,t2);
    if (DIR > 0){
        x[1] = make_float2(t1.x + t3.y, t1.y - t3.x);
        x[3] = make_float2(t1.x - t3.y, t1.y + t3.x);
    } else {
        x[1] = make_float2(t1.x - t3.y, t1.y + t3.x);
        x[3] = make_float2(t1.x + t3.y, t1.y - t3.x);
    }
}
template<int DIR>
__device__ __forceinline__ void r5b(float2 x[5]){
    const float C1 =  0.3090169943749474241f, C2 = -0.8090169943749474241f;
    const float S1 =  0.9510565162951535721f, S2 =  0.5877852522924731292f;
    float2 a0 = x[0];
    float2 t1 = cad(x[1],x[4]), t2 = cad(x[2],x[3]);
    float2 t3 = csb(x[1],x[4]), t4 = csb(x[2],x[3]);
    float2 b0 = make_float2(a0.x + t1.x + t2.x, a0.y + t1.y + t2.y);
    float2 m1 = make_float2(fmaf(C1,t1.x, fmaf(C2,t2.x, a0.x)), fmaf(C1,t1.y, fmaf(C2,t2.y, a0.y)));
    float2 m2 = make_float2(fmaf(C2,t1.x, fmaf(C1,t2.x, a0.x)), fmaf(C2,t1.y, fmaf(C1,t2.y, a0.y)));
    float2 w1 = make_float2(fmaf(S1,t3.x,  S2*t4.x), fmaf(S1,t3.y,  S2*t4.y));
    float2 w2 = make_float2(fmaf(S2,t3.x, -S1*t4.x), fmaf(S2,t3.y, -S1*t4.y));
    x[0] = b0;
    if (DIR > 0){
        x[1] = make_float2(m1.x + w1.y, m1.y - w1.x);
        x[4] = make_float2(m1.x - w1.y, m1.y + w1.x);
        x[2] = make_float2(m2.x + w2.y, m2.y - w2.x);
        x[3] = make_float2(m2.x - w2.y, m2.y + w2.x);
    } else {
        x[1] = make_float2(m1.x - w1.y, m1.y + w1.x);
        x[4] = make_float2(m1.x + w1.y, m1.y - w1.x);
        x[2] = make_float2(m2.x - w2.y, m2.y + w2.x);
        x[3] = make_float2(m2.x + w2.y, m2.y - w2.x);
    }
}

// ---- 80-pt middle stages (per lane; A,B lane-local, 4 sub-FFTs of 80) ----
__device__ __forceinline__ void mid_fwd(float2* A, float2* B, const float2* W, int u){
    if (u < 64){
        int s = u >> 4, i = u & 15;
        float2 x[5];
        #pragma unroll
        for (int j = 0; j < 5; j++) x[j] = A[84*s + i + 16*j];
        r5b<1>(x);
        B[84*s + 5*i] = x[0];
        #pragma unroll
        for (int j = 1; j < 5; j++) B[84*s + 5*i + j] = cml(x[j], tw<1>(W, 4*i*j));
    }
    __syncthreads();
    {
        int s = u/20, v = u%20, p = v/5, q = v%5;
        float2 x[4];
        #pragma unroll
        for (int j = 0; j < 4; j++) x[j] = B[84*s + q + 5*p + 20*j];
        r4b<1>(x);
        A[84*s + q + 20*p] = x[0];
        #pragma unroll
        for (int j = 1; j < 4; j++) A[84*s + q + 20*p + 5*j] = cml(x[j], tw<1>(W, 20*p*j));
    }
    __syncthreads();
}
__device__ __forceinline__ void mid_inv(float2* A, float2* B, const float2* W, int u){
    {
        int s = u/20, v = u%20, p = v/5, q = v%5;
        float2 x[4];
        x[0] = A[84*s + q + 20*p];
        #pragma unroll
        for (int j = 1; j < 4; j++) x[j] = cml(A[84*s + q + 20*p + 5*j], tw<-1>(W, 20*p*j));
        r4b<-1>(x);
        #pragma unroll
        for (int j = 0; j < 4; j++) B[84*s + q + 5*p + 20*j] = x[j];
    }
    __syncthreads();
    if (u < 64){
        int s = u >> 4, i = u & 15;
        float2 x[5];
        x[0] = B[84*s + 5*i];
        #pragma unroll
        for (int j = 1; j < 5; j++) x[j] = cml(B[84*s + 5*i + j], tw<-1>(W, 4*i*j));
        r5b<-1>(x);
        #pragma unroll
        for (int j = 0; j < 5; j++) A[84*s + i + 16*j] = x[j];
    }
    __syncthreads();
}
// F1 (regs->A): x[j] = input at DFT index u+80j
__device__ __forceinline__ void f1_fwd(float2 x[4], float2* A, const float2* W, int u){
    r4b<1>(x);
    A[u] = x[0];
    #pragma unroll
    for (int r = 1; r < 4; r++) A[84*r + u] = cml(x[r], tw<1>(W, u*r));
}
// final fwd (A->regs): y[j] goes to slot u+80j
__device__ __forceinline__ void fin_fwd(const float2* A, float2 y[4], int u){
    int s = u/20, q = u%20;
    #pragma unroll
    for (int j = 0; j < 4; j++) y[j] = A[84*s + q + 20*j];
    r4b<1>(y);
}
// inverse of fin_fwd: y[j] = slot u+80j  ->  A
__device__ __forceinline__ void ifin(float2 y[4], float2* A, int u){
    int s = u/20, q = u%20;
    r4b<-1>(y);
    #pragma unroll
    for (int j = 0; j < 4; j++) A[84*s + q + 20*j] = y[j];
}
// inverse of f1_fwd: A -> z[j] = output at DFT index u+80j
__device__ __forceinline__ void if1(const float2* A, float2 z[4], const float2* W, int u){
    z[0] = A[u];
    #pragma unroll
    for (int r = 1; r < 4; r++) z[r] = cml(A[84*r + u], tw<-1>(W, u*r));
    r4b<-1>(z);
}

__device__ __forceinline__ void reduce320(float v, float* part){
    __shared__ float rb[10];
    int tid = threadIdx.x;
    #pragma unroll
    for (int o = 16; o > 0; o >>= 1) v += __shfl_down_sync(0xffffffffu, v, o);
    if ((tid & 31) == 0) rb[tid >> 5] = v;
    __syncthreads();
    if (tid == 0){
        float t = 0.f;
        #pragma unroll
        for (int i = 0; i < 10; i++) t += rb[i];
        part[blockIdx.x] = t;
    }
}

__global__ void k_init_tw(){
    int k = threadIdx.x;
    double a = -2.0 * 3.14159265358979323846 * (double)k / 320.0;
    d_W[k] = make_float2((float)cos(a), (float)sin(a));
}
__global__ void __launch_bounds__(256) k_maskP(const float* __restrict__ mask, float scale){
    int idx = blockIdx.x*256 + threadIdx.x;
    int hs = idx % NN, ws = (idx/NN) % NN, s = idx / NPIX;
    d_maskPT[idx] = mask[(s*NN + rot160(Pmap(hs)))*NN + rot160(Pmap(ws))] * scale;
}

// ---- K1: row fwd FFT of csm*p (ishift folded on load), permuted slot store ----
__global__ void __launch_bounds__(320) k_fwd_row(const float2* __restrict__ csm,
                                                 const float2* __restrict__ pin){
    __shared__ float2 Ab[4*LS], Bb[4*LS], Wsh[NN];
    int tid = threadIdx.x, lane = tid/80, u = tid%80;
    Wsh[tid] = d_W[tid];
    float2 *A = Ab + lane*LS, *B = Bb + lane*LS;
    int bid = blockIdx.x, g = bid/80, h0 = (bid%80)*4;
    int s = g >> 4, c = g & 15;
    int hi = rot160(h0 + lane);
    long rowC = (long)(c*NN + hi)*NN, rowP = (long)(s*NN + hi)*NN;
    float2 x[4];
    #pragma unroll
    for (int j = 0; j < 4; j++){
        int w = u + 80*(j ^ 2);             // ifftshift fold
        x[j] = cml(csm[rowC + w], pin[rowP + w]);
    }
    __syncthreads();                         // Wsh ready
    f1_fwd(x, A, Wsh, u);
    __syncthreads();
    mid_fwd(A, B, Wsh, u);
    float2 y[4];
    fin_fwd(A, y, u);
    long base = (long)(g*NN + h0 + lane)*NN;
    #pragma unroll
    for (int j = 0; j < 4; j++) d_scr[base + u + 80*j] = y[j];
}

// ---- K2: column fwd FFT + mask (regs, permuted table) + inverse FFT ----
__global__ void __launch_bounds__(320) k_col_ata(){
    __shared__ float2 Ab[4*LS], Bb[4*LS], Wsh[NN];
    int tid = threadIdx.x, lane = tid/80, u = tid%80;
    Wsh[tid] = d_W[tid];
    float2 *A = Ab + lane*LS, *B = Bb + lane*LS;
    int bid = blockIdx.x, g = bid/80, cw0 = (bid%80)*4, sS = g >> 4;
    int e = tid & 1, hh = tid >> 1;
    #pragma unroll
    for (int rr = 0; rr < 2; rr++){
        int h = hh + 160*rr;
        float4 v = *(const float4*)&d_scr[(long)(g*NN + h)*NN + cw0 + 2*e];
        Bb[(2*e)*LS + h]   = make_float2(v.x, v.y);
        Bb[(2*e+1)*LS + h] = make_float2(v.z, v.w);
    }
    __syncthreads();
    float2 x[4];
    #pragma unroll
    for (int j = 0; j < 4; j++) x[j] = B[u + 80*j];   // storage h pre-shifted: no rot
    f1_fwd(x, A, Wsh, u);
    __syncthreads();
    mid_fwd(A, B, Wsh, u);
    float2 y[4];
    fin_fwd(A, y, u);
    long mb = (long)(sS*NN + cw0 + lane)*NN + u;
    #pragma unroll
    for (int j = 0; j < 4; j++){
        float m = d_maskPT[mb + 80*j];
        y[j] = make_float2(y[j].x*m, y[j].y*m);
    }
    ifin(y, A, u);                           // same elements this thread just read
    __syncthreads();
    mid_inv(A, B, Wsh, u);
    float2 z[4];
    if1(A, z, Wsh, u);
    #pragma unroll
    for (int j = 0; j < 4; j++) B[u + 80*j] = z[j];   // storage h = natural n
    __syncthreads();
    #pragma unroll
    for (int rr = 0; rr < 2; rr++){
        int h = hh + 160*rr;
        float2 v0 = Bb[(2*e)*LS + h], v1 = Bb[(2*e+1)*LS + h];
        *(float4*)&d_scr[(long)(g*NN + h)*NN + cw0 + 2*e] = make_float4(v0.x, v0.y, v1.x, v1.y);
    }
}

// ---- K2b (one-time): RHS column inverse FFT of mask*kdata, gathered into slot order ----
__global__ void __launch_bounds__(320) k_col_rhs(const float2* __restrict__ kd,
                                                 const float* __restrict__ mask, float mscale){
    __shared__ float2 Ab[4*LS], Bb[4*LS], Wsh[NN];
    int tid = threadIdx.x, lane = tid/80, u = tid%80;
    Wsh[tid] = d_W[tid];
    float2 *A = Ab + lane*LS, *B = Bb + lane*LS;
    int bid = blockIdx.x, g = bid/80, cw0 = (bid%80)*4, sS = g >> 4;
    int wcol = rot160(Pmap(cw0 + lane));
    float2 y[4];
    #pragma unroll
    for (int j = 0; j < 4; j++){
        int rh = rot160(Pmap(u + 80*j));
        float2 v = kd[(long)(g*NN + rh)*NN + wcol];
        float m = mask[(sS*NN + rh)*NN + wcol] * mscale;
        y[j] = make_float2(v.x*m, v.y*m);
    }
    __syncthreads();
    ifin(y, A, u);
    __syncthreads();
    mid_inv(A, B, Wsh, u);
    float2 z[4];
    if1(A, z, Wsh, u);
    #pragma unroll
    for (int j = 0; j < 4; j++) B[u + 80*j] = z[j];
    __syncthreads();
    int e = tid & 1, hh = tid >> 1;
    #pragma unroll
    for (int rr = 0; rr < 2; rr++){
        int h = hh + 160*rr;
        float2 v0 = Bb[(2*e)*LS + h], v1 = Bb[(2*e+1)*LS + h];
        *(float4*)&d_scr[(long)(g*NN + h)*NN + cw0 + 2*e] = make_float4(v0.x, v0.y, v1.x, v1.y);
    }
}

// ---- K3: row inverse FFT + coil combine (regs) + rho*z + dot ----
__global__ void __launch_bounds__(320) k_inv_row(const float2* __restrict__ csm,
                                                 const float2* __restrict__ z_in,
                                                 float2* __restrict__ out,
                                                 float* __restrict__ part,
                                                 int dotMode, int initMode){
    __shared__ float2 Ab[4*LS], Bb[4*LS], Wsh[NN];
    int tid = threadIdx.x, lane = tid/80, u = tid%80;
    Wsh[tid] = d_W[tid];
    float2 *A = Ab + lane*LS, *B = Bb + lane*LS;
    int bid = blockIdx.x, s = bid/NN, hp = bid%NN;
    int hf = rot160(hp);
    float2 acc[4];
    #pragma unroll
    for (int j = 0; j < 4; j++) acc[j] = make_float2(0.f, 0.f);
    for (int it = 0; it < 4; ++it){
        int c = 4*it + lane, g = s*16 + c;
        float2 y[4];
        long base = (long)(g*NN + hp)*NN;
        #pragma unroll
        for (int j = 0; j < 4; j++) y[j] = d_scr[base + u + 80*j];
        __syncthreads();                   // prev IF1 reads done (and Wsh on it=0)
        ifin(y, A, u);
        __syncthreads();
        mid_inv(A, B, Wsh, u);
        float2 z[4];
        if1(A, z, Wsh, u);
        long cb = (long)(c*NN + hf)*NN + u;
        #pragma unroll
        for (int j = 0; j < 4; j++)        // image w = rot(u+80j) = u+80*(j^2)
            acc[j] = cad(acc[j], cmlcj(z[j], csm[cb + 80*(j ^ 2)]));
    }
    #pragma unroll
    for (int j = 0; j < 4; j++) B[u + 80*(j ^ 2)] = acc[j];
    __syncthreads();
    float2 tot = make_float2(0.f, 0.f);
    #pragma unroll
    for (int l = 0; l < 4; l++) tot = cad(tot, Bb[l*LS + tid]);
    int oi = (s*NN + hf)*NN + tid;
    float2 zv = z_in[oi];
    float2 o = make_float2(fmaf(RHO_F, zv.x, tot.x), fmaf(RHO_F, zv.y, tot.y));
    out[oi] = o;
    if (initMode){ d_p[oi] = o; d_x[oi] = make_float2(0.f, 0.f); }
    float dv = dotMode ? (o.x*o.x + o.y*o.y) : (zv.x*o.x + zv.y*o.y);
    reduce320(dv, part);
}

// ---- scalar finalize + CG updates (unchanged from best) ----
__global__ void __launch_bounds__(1024) k_fin(const float* __restrict__ arrA, int nA,
                                              const float* __restrict__ arrB, int nB, int mode){
    __shared__ float sb[1024];
    int tid = threadIdx.x;
    float v = 0.f;
    for (int i = tid; i < nA; i += 1024) v += arrA[i];
    sb[tid] = v; __syncthreads();
    #pragma unroll
    for (int st = 512; st > 0; st >>= 1){ if (tid < st) sb[tid] += sb[tid+st]; __syncthreads(); }
    float sumA = sb[0];
    __syncthreads();
    float w = 0.f;
    if (nB > 0) for (int i = tid; i < nB; i += 1024) w += arrB[i];
    sb[tid] = w; __syncthreads();
    #pragma unroll
    for (int st = 512; st > 0; st >>= 1){ if (tid < st) sb[tid] += sb[tid+st]; __syncthreads(); }
    if (tid == 0){
        float sumB = sb[0];
        if (mode == 0){
            float rs = (nB > 0) ? sumB : d_sc[0];
            if (nB > 0) d_sc[0] = rs;
            d_sc[1] = rs / (sumA + EPS_F);
        } else { d_sc[2] = sumA / (d_sc[0] + EPS_F); d_sc[0] = sumA; }
    }
}
__global__ void __launch_bounds__(256) k_axpy(float* __restrict__ part,
                                              float2* __restrict__ outp, int last){
    int i = blockIdx.x*256 + threadIdx.x;
    float alpha = d_sc[1];
    float2 pv = d_p[i], xv = d_x[i];
    xv.x = fmaf(alpha, pv.x, xv.x); xv.y = fmaf(alpha, pv.y, xv.y);
    if (last){ outp[i] = xv; return; }
    d_x[i] = xv;
    float2 av = d_Ap[i], rv = d_r[i];
    rv.x = fmaf(-alpha, av.x, rv.x); rv.y = fmaf(-alpha, av.y, rv.y);
    d_r[i] = rv;
    float dv = rv.x*rv.x + rv.y*rv.y;
    __shared__ float rb[8];
    int tid = threadIdx.x;
    #pragma unroll
    for (int o = 16; o > 0; o >>= 1) dv += __shfl_down_sync(0xffffffffu, dv, o);
    if ((tid & 31) == 0) rb[tid >> 5] = dv;
    __syncthreads();
    if (tid == 0){
        float t = 0.f;
        #pragma unroll
        for (int k = 0; k < 8; k++) t += rb[k];
        part[blockIdx.x] = t;
    }
}
__global__ void __launch_bounds__(256) k_updp(){
    int i = blockIdx.x*256 + threadIdx.x;
    float beta = d_sc[2];
    float2 rv = d_r[i], pv = d_p[i];
    d_p[i] = make_float2(fmaf(beta, pv.x, rv.x), fmaf(beta, pv.y, rv.y));
}

extern "C" void kernel_launch(void* const* d_in, const int* in_sizes, int n_in,
                              void* d_out, int out_size){
    const float2* kd = nullptr; const float2* I = nullptr;
    const float2* csm = nullptr; const float* mask = nullptr;
    for (int i = 0; i < n_in; i++){
        int sz = in_sizes[i];
        if      (sz == 13107200) kd   = (const float2*)d_in[i];
        else if (sz == 819200)   I    = (const float2*)d_in[i];
        else if (sz == 3276800)  csm  = (const float2*)d_in[i];
        else if (sz == 409600)   mask = (const float*) d_in[i];
    }
    float2 *rp, *pp, *App; float *partP, *pr;
    cudaGetSymbolAddress((void**)&rp,    d_r);
    cudaGetSymbolAddress((void**)&pp,    d_p);
    cudaGetSymbolAddress((void**)&App,   d_Ap);
    cudaGetSymbolAddress((void**)&partP, d_partP);
    cudaGetSymbolAddress((void**)&pr,    d_pr);

    const float invN  = 1.0f / 320.0f;
    const float invN2 = 1.0f / (320.0f * 320.0f);

    k_init_tw<<<1, 320>>>();                              // #1
    k_maskP<<<1600, 256>>>(mask, invN2);                  // #2
    k_col_rhs<<<5120, 320>>>(kd, mask, invN);             // #3
    k_inv_row<<<1280, 320>>>(csm, I, rp, pr, 1, 1);       // #4

    for (int it = 0; it < 15; ++it){
        int last = (it == 14);
        k_fwd_row<<<5120, 320>>>(csm, pp);                // #5 on iter 0
        k_col_ata<<<5120, 320>>>();                       // #6 -> profiled
        k_inv_row<<<1280, 320>>>(csm, pp, App, partP, 0, 0);
        k_fin<<<1, 1024>>>(partP, 1280, pr, (it == 0) ? 1280 : 0, 0);
        k_axpy<<<1600, 256>>>(pr, (float2*)d_out, last);
        if (!last){
            k_fin<<<1, 1024>>>(pr, 1600, pr, 0, 1);
            k_updp<<<1600, 256>>>();
        }
    }
    (void)out_size;
}

// round 7
// speedup vs baseline: 1.1064x; 1.1064x over previous
#include <cuda_runtime.h>
#include <math.h>

#define NN 320
#define HN 160
#define NPIX (NN*NN)
#define NVEC (4*NPIX)        // 409600 complex
#define RHO_F 0.1f
#define EPS_F 1e-12f

// ---------------- device globals ----------------
__device__ float2 d_scr[64*NPIX];
__device__ float2 d_x[NVEC];
__device__ float2 d_r[NVEC];
__device__ float2 d_p[NVEC];
__device__ float2 d_Ap[NVEC];
__device__ float2 d_W[NN];
__device__ float  d_partP[1280];      // pAp partials
__device__ float  d_pr0[1280];        // |r|^2 partials ping-pong
__device__ float  d_pr1[1280];

// ---------------- complex helpers ----------------
__device__ __forceinline__ float2 cad(float2 a, float2 b){ return make_float2(a.x+b.x, a.y+b.y); }
__device__ __forceinline__ float2 csb(float2 a, float2 b){ return make_float2(a.x-b.x, a.y-b.y); }
__device__ __forceinline__ float2 cml(float2 a, float2 b){
    return make_float2(fmaf(a.x,b.x,-a.y*b.y), fmaf(a.x,b.y, a.y*b.x));
}
__device__ __forceinline__ float2 cmlcj(float2 a, float2 b){
    return make_float2(fmaf(a.x,b.x, a.y*b.y), fmaf(a.y,b.x,-a.x*b.y));
}
template<int DIR>
__device__ __forceinline__ float2 tw(const float2* W, int idx){
    float2 w = W[idx];
    return (DIR > 0) ? w : make_float2(w.x, -w.y);
}
__device__ __forceinline__ int rot160(int j){ return (j < HN) ? j + HN : j - HN; }

// ---------------- Stockham radix-4 stage ----------------
template<int SS, int MM, int DIR>
__device__ __forceinline__ void stage_r4(const float2* src, float2* dst, const float2* W, int u){
    int p = u / SS;
    int q = u - p * SS;
    float2 a0 = src[q + SS*p];
    float2 a1 = src[q + SS*(p + MM)];
    float2 a2 = src[q + SS*(p + 2*MM)];
    float2 a3 = src[q + SS*(p + 3*MM)];
    float2 t0 = cad(a0,a2), t1 = csb(a0,a2), t2 = cad(a1,a3), t3 = csb(a1,a3);
    float2 b0 = cad(t0,t2), b2 = csb(t0,t2);
    float2 b1, b3;
    if (DIR > 0){
        b1 = make_float2(t1.x + t3.y, t1.y - t3.x);
        b3 = make_float2(t1.x - t3.y, t1.y + t3.x);
    } else {
        b1 = make_float2(t1.x - t3.y, t1.y + t3.x);
        b3 = make_float2(t1.x + t3.y, t1.y - t3.x);
    }
    int base = q + SS*4*p;
    dst[base]        = b0;
    dst[base +   SS] = cml(b1, tw<DIR>(W,     SS*p));
    dst[base + 2*SS] = cml(b2, tw<DIR>(W, 2 * SS*p));
    dst[base + 3*SS] = cml(b3, tw<DIR>(W, 3 * SS*p));
}

// ---------------- radix-5 first stage ----------------
template<int DIR>
__device__ __forceinline__ void stage_r5(const float2* A, float2* B, const float2* W, int u){
    if (u < 64){
        float2 a0=A[u], a1=A[u+64], a2=A[u+128], a3=A[u+192], a4=A[u+256];
        const float C1 =  0.3090169943749474241f;
        const float C2 = -0.8090169943749474241f;
        const float S1 =  0.9510565162951535721f;
        const float S2 =  0.5877852522924731292f;
        float2 t1 = cad(a1,a4), t2 = cad(a2,a3), t3 = csb(a1,a4), t4 = csb(a2,a3);
        float2 b0 = make_float2(a0.x + t1.x + t2.x, a0.y + t1.y + t2.y);
        float2 m1 = make_float2(fmaf(C1,t1.x, fmaf(C2,t2.x, a0.x)),
                                fmaf(C1,t1.y, fmaf(C2,t2.y, a0.y)));
        float2 m2 = make_float2(fmaf(C2,t1.x, fmaf(C1,t2.x, a0.x)),
                                fmaf(C2,t1.y, fmaf(C1,t2.y, a0.y)));
        float2 w1 = make_float2(fmaf(S1,t3.x,  S2*t4.x), fmaf(S1,t3.y,  S2*t4.y));
        float2 w2 = make_float2(fmaf(S2,t3.x, -S1*t4.x), fmaf(S2,t3.y, -S1*t4.y));
        float2 b1,b2,b3,b4;
        if (DIR > 0){
            b1 = make_float2(m1.x + w1.y, m1.y - w1.x);
            b4 = make_float2(m1.x - w1.y, m1.y + w1.x);
            b2 = make_float2(m2.x + w2.y, m2.y - w2.x);
            b3 = make_float2(m2.x - w2.y, m2.y + w2.x);
        } else {
            b1 = make_float2(m1.x - w1.y, m1.y + w1.x);
            b4 = make_float2(m1.x + w1.y, m1.y - w1.x);
            b2 = make_float2(m2.x - w2.y, m2.y + w2.x);
            b3 = make_float2(m2.x + w2.y, m2.y - w2.x);
        }
        B[5*u]   = b0;
        B[5*u+1] = cml(b1, tw<DIR>(W,   u));
        B[5*u+2] = cml(b2, tw<DIR>(W, 2*u));
        B[5*u+3] = cml(b3, tw<DIR>(W, 3*u));
        B[5*u+4] = cml(b4, tw<DIR>(W, 4*u));
    }
}

template<int DIR>
__device__ __forceinline__ void fft320(float2* A, float2* B, const float2* W, int u){
    stage_r5<DIR>(A, B, W, u);       __syncthreads();
    stage_r4<5,16,DIR>(B, A, W, u);  __syncthreads();
    stage_r4<20,4,DIR>(A, B, W, u);  __syncthreads();
    stage_r4<80,1,DIR>(B, A, W, u);  __syncthreads();
}
template<int DIR>
__device__ __forceinline__ void fft320_pre(float2* A, float2* B, const float2* W, int u){
    stage_r5<DIR>(A, B, W, u);       __syncthreads();
    stage_r4<5,16,DIR>(B, A, W, u);  __syncthreads();
    stage_r4<20,4,DIR>(A, B, W, u);  __syncthreads();
}
// final radix-4 (unit twiddles) in registers; o[r] -> position u + 80r
template<int DIR>
__device__ __forceinline__ void final_r4(const float2* B, int u, float2 o[4]){
    float2 a0 = B[u], a1 = B[u+80], a2 = B[u+160], a3 = B[u+240];
    float2 t0 = cad(a0,a2), t1 = csb(a0,a2), t2 = cad(a1,a3), t3 = csb(a1,a3);
    o[0] = cad(t0,t2);
    o[2] = csb(t0,t2);
    if (DIR > 0){
        o[1] = make_float2(t1.x + t3.y, t1.y - t3.x);
        o[3] = make_float2(t1.x - t3.y, t1.y + t3.x);
    } else {
        o[1] = make_float2(t1.x - t3.y, t1.y + t3.x);
        o[3] = make_float2(t1.x + t3.y, t1.y - t3.x);
    }
}

// ---------------- reductions ----------------
__device__ __forceinline__ void reduce320(float v, float* part){
    __shared__ float rb[10];
    int tid = threadIdx.x;
    #pragma unroll
    for (int o = 16; o > 0; o >>= 1) v += __shfl_down_sync(0xffffffffu, v, o);
    if ((tid & 31) == 0) rb[tid >> 5] = v;
    __syncthreads();
    if (tid == 0){
        float t = 0.f;
        #pragma unroll
        for (int i = 0; i < 10; i++) t += rb[i];
        part[blockIdx.x] = t;
    }
}
// 1024-thread in-block deterministic sum of array, broadcast to all threads
__device__ __forceinline__ float bsum1024(const float* __restrict__ a, int n){
    __shared__ float rb[32];
    __shared__ float bc;
    int tid = threadIdx.x;
    float v = 0.f;
    for (int i = tid; i < n; i += 1024) v += a[i];
    #pragma unroll
    for (int o = 16; o > 0; o >>= 1) v += __shfl_down_sync(0xffffffffu, v, o);
    if ((tid & 31) == 0) rb[tid >> 5] = v;
    __syncthreads();
    if (tid == 0){
        float t = 0.f;
        #pragma unroll
        for (int k = 0; k < 32; k++) t += rb[k];
        bc = t;
    }
    __syncthreads();
    return bc;
}

// ---------------- init: twiddles ----------------
__global__ void k_init_tw(){
    int k = threadIdx.x;
    double a = -2.0 * 3.14159265358979323846 * (double)k / 320.0;
    d_W[k] = make_float2((float)cos(a), (float)sin(a));
}

// ---------------- K1: forward row FFT of csm*p ----------------
__global__ void __launch_bounds__(320) k_fwd_row(const float2* __restrict__ csm,
                                                 const float2* __restrict__ pin){
    __shared__ float2 Ash[4][321], Bsh[4][321], Wsh[NN];
    int tid = threadIdx.x, lane = tid / 80, u = tid % 80;
    Wsh[tid] = d_W[tid];
    int bid = blockIdx.x;
    int g  = bid / 80;
    int h0 = (bid % 80) * 4;
    int s = g >> 4, c = g & 15;
    int wi = rot160(tid);
    #pragma unroll
    for (int k = 0; k < 4; k++){
        int hi = rot160(h0 + k);
        float2 cv = csm[(c*NN + hi)*NN + wi];
        float2 pv = pin[(s*NN + hi)*NN + wi];
        Ash[k][tid] = cml(cv, pv);
    }
    __syncthreads();
    fft320_pre<1>(Ash[lane], Bsh[lane], Wsh, u);
    float2 o[4];
    final_r4<1>(Bsh[lane], u, o);
    int h = h0 + lane;
    long base = (long)(g*NN + h)*NN;
    #pragma unroll
    for (int r = 0; r < 4; r++)
        d_scr[base + rot160(u + 80*r)] = o[r];
}

// ---------------- K2: fused column fwd FFT + mask (regs) + inv FFT ----------------
__global__ void __launch_bounds__(320) k_col_ata(const float* __restrict__ mask, float mscale){
    __shared__ float2 Ash[4][321], Bsh[4][321], Wsh[NN];
    __shared__ float  Msh[4][320];
    int tid = threadIdx.x, lane = tid / 80, u = tid % 80;
    Wsh[tid] = d_W[tid];
    int bid = blockIdx.x;
    int g = bid / 80;
    int cw0 = (bid % 80) * 4;
    int s = g >> 4;
    int e = tid & 1, hh = tid >> 1;
    {
        int hr = rot160(tid);
        const float4* m4 = (const float4*)(mask + (s*NN + hr)*NN + cw0);
        float4 m = m4[0];
        Msh[0][tid] = m.x*mscale; Msh[1][tid] = m.y*mscale;
        Msh[2][tid] = m.z*mscale; Msh[3][tid] = m.w*mscale;
    }
    #pragma unroll
    for (int rr = 0; rr < 2; rr++){
        int h = hh + 160*rr;
        const float4* s4 = (const float4*)&d_scr[(long)(g*NN + h)*NN + cw0 + 2*e];
        float4 v = s4[0];
        Ash[2*e  ][h] = make_float2(v.x, v.y);
        Ash[2*e+1][h] = make_float2(v.z, v.w);
    }
    __syncthreads();
    fft320_pre<1>(Ash[lane], Bsh[lane], Wsh, u);
    float2 o[4];
    final_r4<1>(Bsh[lane], u, o);
    #pragma unroll
    for (int r = 0; r < 4; r++){
        int j = u + 80*r;
        float m = Msh[lane][j];
        Ash[lane][j] = make_float2(o[r].x*m, o[r].y*m);
    }
    __syncthreads();
    fft320_pre<-1>(Ash[lane], Bsh[lane], Wsh, u);
    final_r4<-1>(Bsh[lane], u, o);
    #pragma unroll
    for (int r = 0; r < 4; r++)
        Ash[lane][u + 80*r] = o[r];
    __syncthreads();
    #pragma unroll
    for (int rr = 0; rr < 2; rr++){
        int h = hh + 160*rr;
        float4* s4 = (float4*)&d_scr[(long)(g*NN + h)*NN + cw0 + 2*e];
        float2 v0 = Ash[2*e][h], v1 = Ash[2*e+1][h];
        s4[0] = make_float4(v0.x, v0.y, v1.x, v1.y);
    }
}

// ---------------- K2b: RHS column inverse FFT of mask*kdata ----------------
__global__ void __launch_bounds__(320) k_col_rhs(const float2* __restrict__ kd,
                                                 const float* __restrict__ mask, float mscale){
    __shared__ float2 Ash[4][321], Bsh[4][321], Wsh[NN];
    int tid = threadIdx.x, lane = tid / 80, u = tid % 80;
    Wsh[tid] = d_W[tid];
    int bid = blockIdx.x;
    int g = bid / 80;
    int cw0 = (bid % 80) * 4;
    int s = g >> 4;
    int e = tid & 1, hh = tid >> 1;
    #pragma unroll
    for (int rr = 0; rr < 2; rr++){
        int j = hh + 160*rr;
        int hr = rot160(j);
        const float4* k4 = (const float4*)&kd[(long)(g*NN + hr)*NN + cw0 + 2*e];
        float4 v = k4[0];
        float m0 = mask[(s*NN + hr)*NN + cw0 + 2*e    ] * mscale;
        float m1 = mask[(s*NN + hr)*NN + cw0 + 2*e + 1] * mscale;
        Ash[2*e  ][j] = make_float2(v.x*m0, v.y*m0);
        Ash[2*e+1][j] = make_float2(v.z*m1, v.w*m1);
    }
    __syncthreads();
    fft320<-1>(Ash[lane], Bsh[lane], Wsh, u);
    #pragma unroll
    for (int rr = 0; rr < 2; rr++){
        int h = hh + 160*rr;
        float4* s4 = (float4*)&d_scr[(long)(g*NN + h)*NN + cw0 + 2*e];
        float2 v0 = Ash[2*e][h], v1 = Ash[2*e+1][h];
        s4[0] = make_float4(v0.x, v0.y, v1.x, v1.y);
    }
}

// ---------------- K3: inverse row FFT + coil combine + rho*z + dot ----------------
__global__ void __launch_bounds__(320) k_inv_row(const float2* __restrict__ csm,
                                                 const float2* __restrict__ z,
                                                 float2* __restrict__ out,
                                                 float* __restrict__ part,
                                                 int dotMode, int initMode){
    __shared__ float2 Ash[4][321], Bsh[4][321], Wsh[NN];
    int tid = threadIdx.x, lane = tid / 80, u = tid % 80;
    Wsh[tid] = d_W[tid];
    int bid = blockIdx.x;
    int s  = bid / NN;
    int hp = bid % NN;
    int hf = rot160(hp);
    int wi = rot160(tid);
    float2 acc = make_float2(0.f, 0.f);
    for (int it = 0; it < 4; ++it){
        __syncthreads();
        #pragma unroll
        for (int k = 0; k < 4; k++){
            int g = s*16 + (k + 4*it);
            Ash[k][tid] = d_scr[(long)(g*NN + hp)*NN + wi];
        }
        __syncthreads();
        fft320<-1>(Ash[lane], Bsh[lane], Wsh, u);
        #pragma unroll
        for (int k = 0; k < 4; k++){
            int c = k + 4*it;
            float2 v  = Ash[k][wi];
            float2 sc = csm[(c*NN + hf)*NN + tid];
            acc = cad(acc, cmlcj(v, sc));
        }
    }
    int oi = (s*NN + hf)*NN + tid;
    float2 zv = z[oi];
    float2 o  = make_float2(fmaf(RHO_F, zv.x, acc.x), fmaf(RHO_F, zv.y, acc.y));
    out[oi] = o;
    if (initMode){
        d_p[oi] = o;
        d_x[oi] = make_float2(0.f, 0.f);
    }
    float dv = dotMode ? (o.x*o.x + o.y*o.y) : (zv.x*o.x + zv.y*o.y);
    reduce320(dv, part);
}

// ---------------- CG updates with in-block scalars ----------------
// alpha = sum(prCur[0:nCur]) / (sum(partP)+eps); x += alpha p;
// if !last: r -= alpha Ap; prNxt[bid] = |r|^2 partial. if last: out = x + alpha p.
__global__ void __launch_bounds__(1024) k_axpy(const float* __restrict__ partP,
                                               const float* __restrict__ prCur, int nCur,
                                               float* __restrict__ prNxt,
                                               float2* __restrict__ outp, int last){
    float rs  = bsum1024(prCur, nCur);
    float pAp = bsum1024(partP, 1280);
    float alpha = rs / (pAp + EPS_F);
    int i = blockIdx.x*1024 + threadIdx.x;
    float2 pv = d_p[i], xv = d_x[i];
    xv.x = fmaf(alpha, pv.x, xv.x); xv.y = fmaf(alpha, pv.y, xv.y);
    if (last){ outp[i] = xv; return; }
    d_x[i] = xv;
    float2 av = d_Ap[i], rv = d_r[i];
    rv.x = fmaf(-alpha, av.x, rv.x); rv.y = fmaf(-alpha, av.y, rv.y);
    d_r[i] = rv;
    float dv = rv.x*rv.x + rv.y*rv.y;
    __shared__ float rb[32];
    int tid = threadIdx.x;
    #pragma unroll
    for (int o = 16; o > 0; o >>= 1) dv += __shfl_down_sync(0xffffffffu, dv, o);
    if ((tid & 31) == 0) rb[tid >> 5] = dv;
    __syncthreads();
    if (tid == 0){
        float t = 0.f;
        #pragma unroll
        for (int k = 0; k < 32; k++) t += rb[k];
        prNxt[blockIdx.x] = t;
    }
}
// beta = sum(prNxt[0:400]) / (sum(prCur[0:nCur])+eps); p = r + beta p
__global__ void __launch_bounds__(1024) k_updp(const float* __restrict__ prCur, int nCur,
                                               const float* __restrict__ prNxt){
    float rsn = bsum1024(prNxt, 400);
    float rso = bsum1024(prCur, nCur);
    float beta = rsn / (rso + EPS_F);
    int i = blockIdx.x*1024 + threadIdx.x;
    float2 rv = d_r[i], pv = d_p[i];
    d_p[i] = make_float2(fmaf(beta, pv.x, rv.x), fmaf(beta, pv.y, rv.y));
}

// ---------------- launch ----------------
extern "C" void kernel_launch(void* const* d_in, const int* in_sizes, int n_in,
                              void* d_out, int out_size){
    const float2* kd = nullptr; const float2* I = nullptr;
    const float2* csm = nullptr; const float* mask = nullptr;
    for (int i = 0; i < n_in; i++){
        int sz = in_sizes[i];
        if      (sz == 13107200) kd   = (const float2*)d_in[i];
        else if (sz == 819200)   I    = (const float2*)d_in[i];
        else if (sz == 3276800)  csm  = (const float2*)d_in[i];
        else if (sz == 409600)   mask = (const float*) d_in[i];
    }
    float2 *rp, *pp, *App; float *partP, *pr0, *pr1;
    cudaGetSymbolAddress((void**)&rp,    d_r);
    cudaGetSymbolAddress((void**)&pp,    d_p);
    cudaGetSymbolAddress((void**)&App,   d_Ap);
    cudaGetSymbolAddress((void**)&partP, d_partP);
    cudaGetSymbolAddress((void**)&pr0,   d_pr0);
    cudaGetSymbolAddress((void**)&pr1,   d_pr1);

    const float invN  = 1.0f / 320.0f;
    const float invN2 = 1.0f / (320.0f * 320.0f);

    k_init_tw<<<1, 320>>>();                              // #1
    k_col_rhs<<<5120, 320>>>(kd, mask, invN);             // #2
    k_inv_row<<<1280, 320>>>(csm, I, rp, pr0, 1, 1);      // #3 (pr0 = 1280 init partials)

    for (int it = 0; it < 15; ++it){
        int last = (it == 14);
        float* cur = (it & 1) ? pr1 : pr0;
        float* nxt = (it & 1) ? pr0 : pr1;
        int nCur = (it == 0) ? 1280 : 400;

        k_fwd_row<<<5120, 320>>>(csm, pp);                // #4 on iter 0 (profiled window)
        k_col_ata<<<5120, 320>>>(mask, invN2);
        k_inv_row<<<1280, 320>>>(csm, pp, App, partP, 0, 0);
        k_axpy<<<400, 1024>>>(partP, cur, nCur, nxt, (float2*)d_out, last);
        if (!last)
            k_updp<<<400, 1024>>>(cur, nCur, nxt);
    }
    (void)out_size;
}

// round 8
// speedup vs baseline: 1.2757x; 1.1530x over previous
#include <cuda_runtime.h>
#include <math.h>

#define NN 320
#define HN 160
#define NPIX (NN*NN)
#define NVEC (4*NPIX)
#define RHO_F 0.1f
#define EPS_F 1e-12f
#define LSZ 360
#define PAD(i) ((i) + ((i) >> 3))

__device__ float2 d_scr[64*NPIX];
__device__ float2 d_x[NVEC];
__device__ float2 d_r[NVEC];
__device__ float2 d_p[NVEC];
__device__ float2 d_Ap[NVEC];
__device__ float2 d_W[NN];
__device__ float  d_partP[1280];
__device__ float  d_pr0[1280];
__device__ float  d_pr1[1280];

__device__ __forceinline__ float2 cad(float2 a, float2 b){ return make_float2(a.x+b.x, a.y+b.y); }
__device__ __forceinline__ float2 csb(float2 a, float2 b){ return make_float2(a.x-b.x, a.y-b.y); }
__device__ __forceinline__ float2 cml(float2 a, float2 b){
    return make_float2(fmaf(a.x,b.x,-a.y*b.y), fmaf(a.x,b.y, a.y*b.x));
}
__device__ __forceinline__ float2 cmlcj(float2 a, float2 b){
    return make_float2(fmaf(a.x,b.x, a.y*b.y), fmaf(a.y,b.x,-a.x*b.y));
}
__device__ __forceinline__ float2 cj(float2 a){ return make_float2(a.x, -a.y); }
template<int DIR>
__device__ __forceinline__ float2 tw(const float2* W, int idx){
    float2 w = W[idx];
    return (DIR > 0) ? w : make_float2(w.x, -w.y);
}
__device__ __forceinline__ int rot160(int j){ return (j < HN) ? j + HN : j - HN; }

template<int DIR>
__device__ __forceinline__ void r4b(float2 x[4]){
    float2 t0 = cad(x[0],x[2]), t1 = csb(x[0],x[2]);
    float2 t2 = cad(x[1],x[3]), t3 = csb(x[1],x[3]);
    x[0] = cad(t0,t2); x[2] = csb(t0,t2);
    if (DIR > 0){
        x[1] = make_float2(t1.x + t3.y, t1.y - t3.x);
        x[3] = make_float2(t1.x - t3.y, t1.y + t3.x);
    } else {
        x[1] = make_float2(t1.x - t3.y, t1.y + t3.x);
        x[3] = make_float2(t1.x + t3.y, t1.y - t3.x);
    }
}
template<int DIR>
__device__ __forceinline__ void r5b(float2 x[5]){
    const float C1 =  0.3090169943749474241f, C2 = -0.8090169943749474241f;
    const float S1 =  0.9510565162951535721f, S2 =  0.5877852522924731292f;
    float2 a0 = x[0];
    float2 t1 = cad(x[1],x[4]), t2 = cad(x[2],x[3]);
    float2 t3 = csb(x[1],x[4]), t4 = csb(x[2],x[3]);
    float2 b0 = make_float2(a0.x + t1.x + t2.x, a0.y + t1.y + t2.y);
    float2 m1 = make_float2(fmaf(C1,t1.x, fmaf(C2,t2.x, a0.x)), fmaf(C1,t1.y, fmaf(C2,t2.y, a0.y)));
    float2 m2 = make_float2(fmaf(C2,t1.x, fmaf(C1,t2.x, a0.x)), fmaf(C2,t1.y, fmaf(C1,t2.y, a0.y)));
    float2 w1 = make_float2(fmaf(S1,t3.x,  S2*t4.x), fmaf(S1,t3.y,  S2*t4.y));
    float2 w2 = make_float2(fmaf(S2,t3.x, -S1*t4.x), fmaf(S2,t3.y, -S1*t4.y));
    x[0] = b0;
    if (DIR > 0){
        x[1] = make_float2(m1.x + w1.y, m1.y - w1.x);
        x[4] = make_float2(m1.x - w1.y, m1.y + w1.x);
        x[2] = make_float2(m2.x + w2.y, m2.y - w2.x);
        x[3] = make_float2(m2.x - w2.y, m2.y + w2.x);
    } else {
        x[1] = make_float2(m1.x - w1.y, m1.y + w1.x);
        x[4] = make_float2(m1.x + w1.y, m1.y - w1.x);
        x[2] = make_float2(m2.x - w2.y, m2.y + w2.x);
        x[3] = make_float2(m2.x + w2.y, m2.y - w2.x);
    }
}

// ---- 8-pt DFT in regs: factors [2,4]; natural in -> natural freq out ----
__device__ __forceinline__ void r8f(float2 v[8]){
    const float S = 0.70710678118654752440f;
    float2 t[8];
    #pragma unroll
    for (int p = 0; p < 4; p++){
        float2 a = v[p], b = v[p+4];
        t[2*p] = cad(a,b);
        float2 d = csb(a,b);
        if      (p == 0) t[1] = d;
        else if (p == 1) t[3] = make_float2(S*(d.x+d.y), S*(d.y-d.x));
        else if (p == 2) t[5] = make_float2(d.y, -d.x);
        else             t[7] = make_float2(S*(d.y-d.x), -S*(d.x+d.y));
    }
    #pragma unroll
    for (int q = 0; q < 2; q++){
        float2 b4[4] = {t[q], t[q+2], t[q+4], t[q+6]};
        r4b<1>(b4);
        v[q] = b4[0]; v[q+2] = b4[1]; v[q+4] = b4[2]; v[q+6] = b4[3];
    }
}
// unnormalized inverse 8-pt (mirror, conj twiddles)
__device__ __forceinline__ void r8i(float2 v[8]){
    const float S = 0.70710678118654752440f;
    float2 t[8];
    #pragma unroll
    for (int q = 0; q < 2; q++){
        float2 b4[4] = {v[q], v[q+2], v[q+4], v[q+6]};
        r4b<-1>(b4);
        t[q] = b4[0]; t[q+2] = b4[1]; t[q+4] = b4[2]; t[q+6] = b4[3];
    }
    #pragma unroll
    for (int p = 0; p < 4; p++){
        float2 a = t[2*p], d = t[2*p+1], b;
        if      (p == 0) b = d;
        else if (p == 1) b = make_float2(S*(d.x-d.y), S*(d.y+d.x));
        else if (p == 2) b = make_float2(-d.y, d.x);
        else             b = make_float2(-S*(d.x+d.y), S*(d.x-d.y));
        v[p]   = cad(a,b);
        v[p+4] = csb(a,b);
    }
}
// w[1..7] = w1^r via balanced chain
__device__ __forceinline__ void twchain7(float2 w1, float2 w[8]){
    w[1] = w1;
    w[2] = cml(w1, w1);
    w[3] = cml(w[2], w1);
    w[4] = cml(w[2], w[2]);
    w[5] = cml(w[4], w1);
    w[6] = cml(w[3], w[3]);
    w[7] = cml(w[4], w[3]);
}

// ---------------- legacy full-smem 320-pt FFT (inv_row / col_rhs) ----------------
template<int SS, int MM, int DIR>
__device__ __forceinline__ void stage_r4(const float2* src, float2* dst, const float2* W, int u){
    int p = u / SS, q = u - p * SS;
    float2 x[4];
    #pragma unroll
    for (int j = 0; j < 4; j++) x[j] = src[q + SS*(p + MM*j)];
    r4b<DIR>(x);
    int base = q + SS*4*p;
    dst[base] = x[0];
    #pragma unroll
    for (int j = 1; j < 4; j++) dst[base + SS*j] = cml(x[j], tw<DIR>(W, SS*p*j));
}
template<int DIR>
__device__ __forceinline__ void stage_r5_old(const float2* A, float2* B, const float2* W, int u){
    if (u < 64){
        float2 x[5];
        #pragma unroll
        for (int j = 0; j < 5; j++) x[j] = A[u + 64*j];
        r5b<DIR>(x);
        B[5*u] = x[0];
        #pragma unroll
        for (int j = 1; j < 5; j++) B[5*u + j] = cml(x[j], tw<DIR>(W, u*j));
    }
}
template<int DIR>
__device__ __forceinline__ void fft320(float2* A, float2* B, const float2* W, int u){
    stage_r5_old<DIR>(A, B, W, u);   __syncthreads();
    stage_r4<5,16,DIR>(B, A, W, u);  __syncthreads();
    stage_r4<20,4,DIR>(A, B, W, u);  __syncthreads();
    stage_r4<80,1,DIR>(B, A, W, u);  __syncthreads();
}

// ---------------- reductions ----------------
__device__ __forceinline__ void reduce320(float v, float* part){
    __shared__ float rb[10];
    int tid = threadIdx.x;
    #pragma unroll
    for (int o = 16; o > 0; o >>= 1) v += __shfl_down_sync(0xffffffffu, v, o);
    if ((tid & 31) == 0) rb[tid >> 5] = v;
    __syncthreads();
    if (tid == 0){
        float t = 0.f;
        #pragma unroll
        for (int i = 0; i < 10; i++) t += rb[i];
        part[blockIdx.x] = t;
    }
}
__device__ __forceinline__ float bsum1024(const float* __restrict__ a, int n){
    __shared__ float rb[32];
    __shared__ float bc;
    int tid = threadIdx.x;
    float v = 0.f;
    for (int i = tid; i < n; i += 1024) v += a[i];
    #pragma unroll
    for (int o = 16; o > 0; o >>= 1) v += __shfl_down_sync(0xffffffffu, v, o);
    if ((tid & 31) == 0) rb[tid >> 5] = v;
    __syncthreads();
    if (tid == 0){
        float t = 0.f;
        #pragma unroll
        for (int k = 0; k < 32; k++) t += rb[k];
        bc = t;
    }
    __syncthreads();
    return bc;
}

__global__ void k_init_tw(){
    int k = threadIdx.x;
    double a = -2.0 * 3.14159265358979323846 * (double)k / 320.0;
    d_W[k] = make_float2((float)cos(a), (float)sin(a));
}

// ---------------- K1: row fwd FFT of csm*p, radix [8,8,5], 2 smem rounds ----------------
__global__ void __launch_bounds__(320, 4) k_fwd_row(const float2* __restrict__ csm,
                                                    const float2* __restrict__ pin){
    __shared__ float2 SA[4*LSZ], SB[4*LSZ], Wsh[NN];
    int tid = threadIdx.x;
    Wsh[tid] = d_W[tid];
    int bid = blockIdx.x;
    int g  = bid / 80;
    int h0 = (bid % 80) * 4;
    int s = g >> 4, c = g & 15;
    __syncthreads();
    // S1: radix-8 from global (ifftshift folded), 160 threads
    if (tid < 160){
        int fi = tid / 40, p = tid % 40;
        int hi = rot160(h0 + fi);
        long rowC = (long)(c*NN + hi)*NN, rowP = (long)(s*NN + hi)*NN;
        float2 v[8];
        #pragma unroll
        for (int j = 0; j < 8; j++){
            int w = p + 40*((j + 4) & 7);
            v[j] = cml(csm[rowC + w], pin[rowP + w]);
        }
        r8f(v);
        float2 w[8]; twchain7(Wsh[p], w);
        float2* B = SB + fi*LSZ;
        B[PAD(8*p)] = v[0];
        #pragma unroll
        for (int r = 1; r < 8; r++) B[PAD(8*p + r)] = cml(v[r], w[r]);
    }
    __syncthreads();
    // S2: radix-8, 160 threads
    if (tid < 160){
        int fi = tid / 40, u = tid % 40, q = u & 7, p = u >> 3;
        float2* A = SA + fi*LSZ;
        float2* B = SB + fi*LSZ;
        float2 v[8];
        #pragma unroll
        for (int j = 0; j < 8; j++) v[j] = B[PAD(q + 8*p + 40*j)];
        r8f(v);
        float2 w[8]; twchain7(Wsh[8*p], w);
        A[PAD(q + 64*p)] = v[0];
        #pragma unroll
        for (int r = 1; r < 8; r++) A[PAD(q + 64*p + 8*r)] = cml(v[r], w[r]);
    }
    __syncthreads();
    // S3: radix-5 final (unit tw) -> global at rot160(freq)
    if (tid < 256){
        int fi = tid >> 6, q = tid & 63;
        float2* A = SA + fi*LSZ;
        float2 x[5];
        #pragma unroll
        for (int j = 0; j < 5; j++) x[j] = A[PAD(q + 64*j)];
        r5b<1>(x);
        long base = (long)(g*NN + h0 + fi)*NN;
        #pragma unroll
        for (int j = 0; j < 5; j++){
            int f = q + 64*j;
            d_scr[base + (f < HN ? f + HN : f - HN)] = x[j];
        }
    }
}

// ---------------- K2: column fwd FFT + mask (regs) + inverse FFT, radix [8,8,5] ----------------
__global__ void __launch_bounds__(320, 4) k_col_ata(const float* __restrict__ mask, float mscale){
    __shared__ float2 SA[4*LSZ], SB[4*LSZ], Wsh[NN];
    __shared__ float  Msh[4][320];
    int tid = threadIdx.x;
    Wsh[tid] = d_W[tid];
    int bid = blockIdx.x;
    int g = bid / 80;
    int cw0 = (bid % 80) * 4;
    int s = g >> 4;
    int e = tid & 1, hh = tid >> 1;
    {   // mask table indexed by FREQ (rot folded at load)
        int hr = rot160(tid);
        float4 m = *(const float4*)(mask + (s*NN + hr)*NN + cw0);
        Msh[0][tid] = m.x*mscale; Msh[1][tid] = m.y*mscale;
        Msh[2][tid] = m.z*mscale; Msh[3][tid] = m.w*mscale;
    }
    #pragma unroll
    for (int rr = 0; rr < 2; rr++){
        int h = hh + 160*rr;
        float4 v = *(const float4*)&d_scr[(long)(g*NN + h)*NN + cw0 + 2*e];
        SA[(2*e)*LSZ + h]   = make_float2(v.x, v.y);
        SA[(2*e+1)*LSZ + h] = make_float2(v.z, v.w);
    }
    __syncthreads();
    // S1 fwd
    if (tid < 160){
        int fi = tid / 40, p = tid % 40;
        float2* A = SA + fi*LSZ;
        float2* B = SB + fi*LSZ;
        float2 v[8];
        #pragma unroll
        for (int j = 0; j < 8; j++) v[j] = A[p + 40*j];
        r8f(v);
        float2 w[8]; twchain7(Wsh[p], w);
        B[PAD(8*p)] = v[0];
        #pragma unroll
        for (int r = 1; r < 8; r++) B[PAD(8*p + r)] = cml(v[r], w[r]);
    }
    __syncthreads();
    // S2 fwd
    if (tid < 160){
        int fi = tid / 40, u = tid % 40, q = u & 7, p = u >> 3;
        float2* A = SA + fi*LSZ;
        float2* B = SB + fi*LSZ;
        float2 v[8];
        #pragma unroll
        for (int j = 0; j < 8; j++) v[j] = B[PAD(q + 8*p + 40*j)];
        r8f(v);
        float2 w[8]; twchain7(Wsh[8*p], w);
        A[PAD(q + 64*p)] = v[0];
        #pragma unroll
        for (int r = 1; r < 8; r++) A[PAD(q + 64*p + 8*r)] = cml(v[r], w[r]);
    }
    __syncthreads();
    // S3 fwd + mask + iS3 (same thread, same addresses -> no extra sync before write)
    if (tid < 256){
        int fi = tid >> 6, q = tid & 63;
        float2* A = SA + fi*LSZ;
        float2 x[5];
        #pragma unroll
        for (int j = 0; j < 5; j++) x[j] = A[PAD(q + 64*j)];
        r5b<1>(x);
        #pragma unroll
        for (int j = 0; j < 5; j++){
            float m = Msh[fi][q + 64*j];
            x[j] = make_float2(x[j].x*m, x[j].y*m);
        }
        r5b<-1>(x);
        #pragma unroll
        for (int j = 0; j < 5; j++) A[PAD(q + 64*j)] = x[j];
    }
    __syncthreads();
    // iS2
    if (tid < 160){
        int fi = tid / 40, u = tid % 40, q = u & 7, p = u >> 3;
        float2* A = SA + fi*LSZ;
        float2* B = SB + fi*LSZ;
        float2 w[8]; twchain7(cj(Wsh[8*p]), w);
        float2 v[8];
        v[0] = A[PAD(q + 64*p)];
        #pragma unroll
        for (int r = 1; r < 8; r++) v[r] = cml(A[PAD(q + 64*p + 8*r)], w[r]);
        r8i(v);
        #pragma unroll
        for (int j = 0; j < 8; j++) B[PAD(q + 8*p + 40*j)] = v[j];
    }
    __syncthreads();
    // iS1 -> staging (plain layout)
    if (tid < 160){
        int fi = tid / 40, p = tid % 40;
        float2* A = SA + fi*LSZ;
        float2* B = SB + fi*LSZ;
        float2 w[8]; twchain7(cj(Wsh[p]), w);
        float2 v[8];
        v[0] = B[PAD(8*p)];
        #pragma unroll
        for (int r = 1; r < 8; r++) v[r] = cml(B[PAD(8*p + r)], w[r]);
        r8i(v);
        #pragma unroll
        for (int j = 0; j < 8; j++) A[p + 40*j] = v[j];
    }
    __syncthreads();
    #pragma unroll
    for (int rr = 0; rr < 2; rr++){
        int h = hh + 160*rr;
        float2 v0 = SA[(2*e)*LSZ + h], v1 = SA[(2*e+1)*LSZ + h];
        *(float4*)&d_scr[(long)(g*NN + h)*NN + cw0 + 2*e] = make_float4(v0.x, v0.y, v1.x, v1.y);
    }
}

// ---------------- K2b: RHS column inverse FFT of mask*kdata (legacy path) ----------------
__global__ void __launch_bounds__(320) k_col_rhs(const float2* __restrict__ kd,
                                                 const float* __restrict__ mask, float mscale){
    __shared__ float2 Ash[4][321], Bsh[4][321], Wsh[NN];
    int tid = threadIdx.x, lane = tid / 80, u = tid % 80;
    Wsh[tid] = d_W[tid];
    int bid = blockIdx.x;
    int g = bid / 80;
    int cw0 = (bid % 80) * 4;
    int s = g >> 4;
    int e = tid & 1, hh = tid >> 1;
    #pragma unroll
    for (int rr = 0; rr < 2; rr++){
        int j = hh + 160*rr;
        int hr = rot160(j);
        const float4* k4 = (const float4*)&kd[(long)(g*NN + hr)*NN + cw0 + 2*e];
        float4 v = k4[0];
        float m0 = mask[(s*NN + hr)*NN + cw0 + 2*e    ] * mscale;
        float m1 = mask[(s*NN + hr)*NN + cw0 + 2*e + 1] * mscale;
        Ash[2*e  ][j] = make_float2(v.x*m0, v.y*m0);
        Ash[2*e+1][j] = make_float2(v.z*m1, v.w*m1);
    }
    __syncthreads();
    fft320<-1>(Ash[lane], Bsh[lane], Wsh, u);
    #pragma unroll
    for (int rr = 0; rr < 2; rr++){
        int h = hh + 160*rr;
        float4* s4 = (float4*)&d_scr[(long)(g*NN + h)*NN + cw0 + 2*e];
        float2 v0 = Ash[2*e][h], v1 = Ash[2*e+1][h];
        s4[0] = make_float4(v0.x, v0.y, v1.x, v1.y);
    }
}

// ---------------- K3: inverse row FFT + coil combine + rho*z + dot (legacy path) ----------------
__global__ void __launch_bounds__(320) k_inv_row(const float2* __restrict__ csm,
                                                 const float2* __restrict__ z,
                                                 float2* __restrict__ out,
                                                 float* __restrict__ part,
                                                 int dotMode, int initMode){
    __shared__ float2 Ash[4][321], Bsh[4][321], Wsh[NN];
    int tid = threadIdx.x, lane = tid / 80, u = tid % 80;
    Wsh[tid] = d_W[tid];
    int bid = blockIdx.x;
    int s  = bid / NN;
    int hp = bid % NN;
    int hf = rot160(hp);
    int wi = rot160(tid);
    float2 acc = make_float2(0.f, 0.f);
    for (int it = 0; it < 4; ++it){
        __syncthreads();
        #pragma unroll
        for (int k = 0; k < 4; k++){
            int g = s*16 + (k + 4*it);
            Ash[k][tid] = d_scr[(long)(g*NN + hp)*NN + wi];
        }
        __syncthreads();
        fft320<-1>(Ash[lane], Bsh[lane], Wsh, u);
        #pragma unroll
        for (int k = 0; k < 4; k++){
            int c = k + 4*it;
            float2 v  = Ash[k][wi];
            float2 sc = csm[(c*NN + hf)*NN + tid];
            acc = cad(acc, cmlcj(v, sc));
        }
    }
    int oi = (s*NN + hf)*NN + tid;
    float2 zv = z[oi];
    float2 o  = make_float2(fmaf(RHO_F, zv.x, acc.x), fmaf(RHO_F, zv.y, acc.y));
    out[oi] = o;
    if (initMode){
        d_p[oi] = o;
        d_x[oi] = make_float2(0.f, 0.f);
    }
    float dv = dotMode ? (o.x*o.x + o.y*o.y) : (zv.x*o.x + zv.y*o.y);
    reduce320(dv, part);
}

// ---------------- CG updates with in-block scalars ----------------
__global__ void __launch_bounds__(1024) k_axpy(const float* __restrict__ partP,
                                               const float* __restrict__ prCur, int nCur,
                                               float* __restrict__ prNxt,
                                               float2* __restrict__ outp, int last){
    float rs  = bsum1024(prCur, nCur);
    float pAp = bsum1024(partP, 1280);
    float alpha = rs / (pAp + EPS_F);
    int i = blockIdx.x*1024 + threadIdx.x;
    float2 pv = d_p[i], xv = d_x[i];
    xv.x = fmaf(alpha, pv.x, xv.x); xv.y = fmaf(alpha, pv.y, xv.y);
    if (last){ outp[i] = xv; return; }
    d_x[i] = xv;
    float2 av = d_Ap[i], rv = d_r[i];
    rv.x = fmaf(-alpha, av.x, rv.x); rv.y = fmaf(-alpha, av.y, rv.y);
    d_r[i] = rv;
    float dv = rv.x*rv.x + rv.y*rv.y;
    __shared__ float rb[32];
    int tid = threadIdx.x;
    #pragma unroll
    for (int o = 16; o > 0; o >>= 1) dv += __shfl_down_sync(0xffffffffu, dv, o);
    if ((tid & 31) == 0) rb[tid >> 5] = dv;
    __syncthreads();
    if (tid == 0){
        float t = 0.f;
        #pragma unroll
        for (int k = 0; k < 32; k++) t += rb[k];
        prNxt[blockIdx.x] = t;
    }
}
__global__ void __launch_bounds__(1024) k_updp(const float* __restrict__ prCur, int nCur,
                                               const float* __restrict__ prNxt){
    float rsn = bsum1024(prNxt, 400);
    float rso = bsum1024(prCur, nCur);
    float beta = rsn / (rso + EPS_F);
    int i = blockIdx.x*1024 + threadIdx.x;
    float2 rv = d_r[i], pv = d_p[i];
    d_p[i] = make_float2(fmaf(beta, pv.x, rv.x), fmaf(beta, pv.y, rv.y));
}

// ---------------- launch ----------------
extern "C" void kernel_launch(void* const* d_in, const int* in_sizes, int n_in,
                              void* d_out, int out_size){
    const float2* kd = nullptr; const float2* I = nullptr;
    const float2* csm = nullptr; const float* mask = nullptr;
    for (int i = 0; i < n_in; i++){
        int sz = in_sizes[i];
        if      (sz == 13107200) kd   = (const float2*)d_in[i];
        else if (sz == 819200)   I    = (const float2*)d_in[i];
        else if (sz == 3276800)  csm  = (const float2*)d_in[i];
        else if (sz == 409600)   mask = (const float*) d_in[i];
    }
    float2 *rp, *pp, *App; float *partP, *pr0, *pr1;
    cudaGetSymbolAddress((void**)&rp,    d_r);
    cudaGetSymbolAddress((void**)&pp,    d_p);
    cudaGetSymbolAddress((void**)&App,   d_Ap);
    cudaGetSymbolAddress((void**)&partP, d_partP);
    cudaGetSymbolAddress((void**)&pr0,   d_pr0);
    cudaGetSymbolAddress((void**)&pr1,   d_pr1);

    const float invN  = 1.0f / 320.0f;
    const float invN2 = 1.0f / (320.0f * 320.0f);

    k_init_tw<<<1, 320>>>();
    k_col_rhs<<<5120, 320>>>(kd, mask, invN);
    k_inv_row<<<1280, 320>>>(csm, I, rp, pr0, 1, 1);

    for (int it = 0; it < 15; ++it){
        int last = (it == 14);
        float* cur = (it & 1) ? pr1 : pr0;
        float* nxt = (it & 1) ? pr0 : pr1;
        int nCur = (it == 0) ? 1280 : 400;

        k_fwd_row<<<5120, 320>>>(csm, pp);        // launch #4 on iter 0 -> profiled
        k_col_ata<<<5120, 320>>>(mask, invN2);
        k_inv_row<<<1280, 320>>>(csm, pp, App, partP, 0, 0);
        k_axpy<<<400, 1024>>>(partP, cur, nCur, nxt, (float2*)d_out, last);
        if (!last)
            k_updp<<<400, 1024>>>(cur, nCur, nxt);
    }
    (void)out_size;
}

// round 9
// speedup vs baseline: 1.2837x; 1.0062x over previous
#include <cuda_runtime.h>
#include <math.h>

#define NN 320
#define HN 160
#define NPIX (NN*NN)
#define NVEC (4*NPIX)
#define RHO_F 0.1f
#define EPS_F 1e-12f
#define LSZ 360
#define PAD(i) ((i) + ((i) >> 3))

__device__ float2 d_scr[64*NPIX];
__device__ float2 d_x[NVEC];
__device__ float2 d_r[NVEC];
__device__ float2 d_p[NVEC];
__device__ float2 d_Ap[NVEC];
__device__ float2 d_W[NN];
__device__ float  d_partP[1280];
__device__ float  d_pr0[1280];
__device__ float  d_pr1[1280];

__device__ __forceinline__ float2 cad(float2 a, float2 b){ return make_float2(a.x+b.x, a.y+b.y); }
__device__ __forceinline__ float2 csb(float2 a, float2 b){ return make_float2(a.x-b.x, a.y-b.y); }
__device__ __forceinline__ float2 cml(float2 a, float2 b){
    return make_float2(fmaf(a.x,b.x,-a.y*b.y), fmaf(a.x,b.y, a.y*b.x));
}
__device__ __forceinline__ float2 cmlcj(float2 a, float2 b){
    return make_float2(fmaf(a.x,b.x, a.y*b.y), fmaf(a.y,b.x,-a.x*b.y));
}
__device__ __forceinline__ float2 cj(float2 a){ return make_float2(a.x, -a.y); }
template<int DIR>
__device__ __forceinline__ float2 tw(const float2* W, int idx){
    float2 w = W[idx];
    return (DIR > 0) ? w : make_float2(w.x, -w.y);
}
__device__ __forceinline__ int rot160(int j){ return (j < HN) ? j + HN : j - HN; }

template<int DIR>
__device__ __forceinline__ void r4b(float2 x[4]){
    float2 t0 = cad(x[0],x[2]), t1 = csb(x[0],x[2]);
    float2 t2 = cad(x[1],x[3]), t3 = csb(x[1],x[3]);
    x[0] = cad(t0,t2); x[2] = csb(t0,t2);
    if (DIR > 0){
        x[1] = make_float2(t1.x + t3.y, t1.y - t3.x);
        x[3] = make_float2(t1.x - t3.y, t1.y + t3.x);
    } else {
        x[1] = make_float2(t1.x - t3.y, t1.y + t3.x);
        x[3] = make_float2(t1.x + t3.y, t1.y - t3.x);
    }
}
template<int DIR>
__device__ __forceinline__ void r5b(float2 x[5]){
    const float C1 =  0.3090169943749474241f, C2 = -0.8090169943749474241f;
    const float S1 =  0.9510565162951535721f, S2 =  0.5877852522924731292f;
    float2 a0 = x[0];
    float2 t1 = cad(x[1],x[4]), t2 = cad(x[2],x[3]);
    float2 t3 = csb(x[1],x[4]), t4 = csb(x[2],x[3]);
    float2 b0 = make_float2(a0.x + t1.x + t2.x, a0.y + t1.y + t2.y);
    float2 m1 = make_float2(fmaf(C1,t1.x, fmaf(C2,t2.x, a0.x)), fmaf(C1,t1.y, fmaf(C2,t2.y, a0.y)));
    float2 m2 = make_float2(fmaf(C2,t1.x, fmaf(C1,t2.x, a0.x)), fmaf(C2,t1.y, fmaf(C1,t2.y, a0.y)));
    float2 w1 = make_float2(fmaf(S1,t3.x,  S2*t4.x), fmaf(S1,t3.y,  S2*t4.y));
    float2 w2 = make_float2(fmaf(S2,t3.x, -S1*t4.x), fmaf(S2,t3.y, -S1*t4.y));
    x[0] = b0;
    if (DIR > 0){
        x[1] = make_float2(m1.x + w1.y, m1.y - w1.x);
        x[4] = make_float2(m1.x - w1.y, m1.y + w1.x);
        x[2] = make_float2(m2.x + w2.y, m2.y - w2.x);
        x[3] = make_float2(m2.x - w2.y, m2.y + w2.x);
    } else {
        x[1] = make_float2(m1.x - w1.y, m1.y + w1.x);
        x[4] = make_float2(m1.x + w1.y, m1.y - w1.x);
        x[2] = make_float2(m2.x - w2.y, m2.y + w2.x);
        x[3] = make_float2(m2.x + w2.y, m2.y - w2.x);
    }
}

// ---- 8-pt DFT in regs ----
__device__ __forceinline__ void r8f(float2 v[8]){
    const float S = 0.70710678118654752440f;
    float2 t[8];
    #pragma unroll
    for (int p = 0; p < 4; p++){
        float2 a = v[p], b = v[p+4];
        t[2*p] = cad(a,b);
        float2 d = csb(a,b);
        if      (p == 0) t[1] = d;
        else if (p == 1) t[3] = make_float2(S*(d.x+d.y), S*(d.y-d.x));
        else if (p == 2) t[5] = make_float2(d.y, -d.x);
        else             t[7] = make_float2(S*(d.y-d.x), -S*(d.x+d.y));
    }
    #pragma unroll
    for (int q = 0; q < 2; q++){
        float2 b4[4] = {t[q], t[q+2], t[q+4], t[q+6]};
        r4b<1>(b4);
        v[q] = b4[0]; v[q+2] = b4[1]; v[q+4] = b4[2]; v[q+6] = b4[3];
    }
}
__device__ __forceinline__ void r8i(float2 v[8]){
    const float S = 0.70710678118654752440f;
    float2 t[8];
    #pragma unroll
    for (int q = 0; q < 2; q++){
        float2 b4[4] = {v[q], v[q+2], v[q+4], v[q+6]};
        r4b<-1>(b4);
        t[q] = b4[0]; t[q+2] = b4[1]; t[q+4] = b4[2]; t[q+6] = b4[3];
    }
    #pragma unroll
    for (int p = 0; p < 4; p++){
        float2 a = t[2*p], d = t[2*p+1], b;
        if      (p == 0) b = d;
        else if (p == 1) b = make_float2(S*(d.x-d.y), S*(d.y+d.x));
        else if (p == 2) b = make_float2(-d.y, d.x);
        else             b = make_float2(-S*(d.x+d.y), S*(d.x-d.y));
        v[p]   = cad(a,b);
        v[p+4] = csb(a,b);
    }
}
__device__ __forceinline__ void twchain7(float2 w1, float2 w[8]){
    w[1] = w1;
    w[2] = cml(w1, w1);
    w[3] = cml(w[2], w1);
    w[4] = cml(w[2], w[2]);
    w[5] = cml(w[4], w1);
    w[6] = cml(w[3], w[3]);
    w[7] = cml(w[4], w[3]);
}

// ---------------- legacy full-smem 320-pt FFT (col_rhs only) ----------------
template<int SS, int MM, int DIR>
__device__ __forceinline__ void stage_r4(const float2* src, float2* dst, const float2* W, int u){
    int p = u / SS, q = u - p * SS;
    float2 x[4];
    #pragma unroll
    for (int j = 0; j < 4; j++) x[j] = src[q + SS*(p + MM*j)];
    r4b<DIR>(x);
    int base = q + SS*4*p;
    dst[base] = x[0];
    #pragma unroll
    for (int j = 1; j < 4; j++) dst[base + SS*j] = cml(x[j], tw<DIR>(W, SS*p*j));
}
template<int DIR>
__device__ __forceinline__ void stage_r5_old(const float2* A, float2* B, const float2* W, int u){
    if (u < 64){
        float2 x[5];
        #pragma unroll
        for (int j = 0; j < 5; j++) x[j] = A[u + 64*j];
        r5b<DIR>(x);
        B[5*u] = x[0];
        #pragma unroll
        for (int j = 1; j < 5; j++) B[5*u + j] = cml(x[j], tw<DIR>(W, u*j));
    }
}
template<int DIR>
__device__ __forceinline__ void fft320(float2* A, float2* B, const float2* W, int u){
    stage_r5_old<DIR>(A, B, W, u);   __syncthreads();
    stage_r4<5,16,DIR>(B, A, W, u);  __syncthreads();
    stage_r4<20,4,DIR>(A, B, W, u);  __syncthreads();
    stage_r4<80,1,DIR>(B, A, W, u);  __syncthreads();
}

// ---------------- reductions ----------------
__device__ __forceinline__ void reduce320(float v, float* part){
    __shared__ float rb[10];
    int tid = threadIdx.x;
    #pragma unroll
    for (int o = 16; o > 0; o >>= 1) v += __shfl_down_sync(0xffffffffu, v, o);
    if ((tid & 31) == 0) rb[tid >> 5] = v;
    __syncthreads();
    if (tid == 0){
        float t = 0.f;
        #pragma unroll
        for (int i = 0; i < 10; i++) t += rb[i];
        part[blockIdx.x] = t;
    }
}
__device__ __forceinline__ float bsum1024(const float* __restrict__ a, int n){
    __shared__ float rb[32];
    __shared__ float bc;
    int tid = threadIdx.x;
    float v = 0.f;
    for (int i = tid; i < n; i += 1024) v += a[i];
    #pragma unroll
    for (int o = 16; o > 0; o >>= 1) v += __shfl_down_sync(0xffffffffu, v, o);
    if ((tid & 31) == 0) rb[tid >> 5] = v;
    __syncthreads();
    if (tid == 0){
        float t = 0.f;
        #pragma unroll
        for (int k = 0; k < 32; k++) t += rb[k];
        bc = t;
    }
    __syncthreads();
    return bc;
}

__global__ void k_init_tw(){
    int k = threadIdx.x;
    double a = -2.0 * 3.14159265358979323846 * (double)k / 320.0;
    d_W[k] = make_float2((float)cos(a), (float)sin(a));
}

// ---------------- K1: row fwd FFT of csm*p, radix [8,8,5] ----------------
__global__ void __launch_bounds__(320, 4) k_fwd_row(const float2* __restrict__ csm,
                                                    const float2* __restrict__ pin){
    __shared__ float2 SA[4*LSZ], SB[4*LSZ], Wsh[NN];
    int tid = threadIdx.x;
    Wsh[tid] = d_W[tid];
    int bid = blockIdx.x;
    int g  = bid / 80;
    int h0 = (bid % 80) * 4;
    int s = g >> 4, c = g & 15;
    __syncthreads();
    if (tid < 160){
        int fi = tid / 40, p = tid % 40;
        int hi = rot160(h0 + fi);
        long rowC = (long)(c*NN + hi)*NN, rowP = (long)(s*NN + hi)*NN;
        float2 v[8];
        #pragma unroll
        for (int j = 0; j < 8; j++){
            int w = p + 40*((j + 4) & 7);
            v[j] = cml(csm[rowC + w], pin[rowP + w]);
        }
        r8f(v);
        float2 w[8]; twchain7(Wsh[p], w);
        float2* B = SB + fi*LSZ;
        B[PAD(8*p)] = v[0];
        #pragma unroll
        for (int r = 1; r < 8; r++) B[PAD(8*p + r)] = cml(v[r], w[r]);
    }
    __syncthreads();
    if (tid < 160){
        int fi = tid / 40, u = tid % 40, q = u & 7, p = u >> 3;
        float2* A = SA + fi*LSZ;
        float2* B = SB + fi*LSZ;
        float2 v[8];
        #pragma unroll
        for (int j = 0; j < 8; j++) v[j] = B[PAD(q + 8*p + 40*j)];
        r8f(v);
        float2 w[8]; twchain7(Wsh[8*p], w);
        A[PAD(q + 64*p)] = v[0];
        #pragma unroll
        for (int r = 1; r < 8; r++) A[PAD(q + 64*p + 8*r)] = cml(v[r], w[r]);
    }
    __syncthreads();
    if (tid < 256){
        int fi = tid >> 6, q = tid & 63;
        float2* A = SA + fi*LSZ;
        float2 x[5];
        #pragma unroll
        for (int j = 0; j < 5; j++) x[j] = A[PAD(q + 64*j)];
        r5b<1>(x);
        long base = (long)(g*NN + h0 + fi)*NN;
        #pragma unroll
        for (int j = 0; j < 5; j++){
            int f = q + 64*j;
            d_scr[base + (f < HN ? f + HN : f - HN)] = x[j];
        }
    }
}

// ---------------- K2: column fwd + mask + inverse, radix [8,8,5] ----------------
__global__ void __launch_bounds__(320, 4) k_col_ata(const float* __restrict__ mask, float mscale){
    __shared__ float2 SA[4*LSZ], SB[4*LSZ], Wsh[NN];
    __shared__ float  Msh[4][320];
    int tid = threadIdx.x;
    Wsh[tid] = d_W[tid];
    int bid = blockIdx.x;
    int g = bid / 80;
    int cw0 = (bid % 80) * 4;
    int s = g >> 4;
    int e = tid & 1, hh = tid >> 1;
    {
        int hr = rot160(tid);
        float4 m = *(const float4*)(mask + (s*NN + hr)*NN + cw0);
        Msh[0][tid] = m.x*mscale; Msh[1][tid] = m.y*mscale;
        Msh[2][tid] = m.z*mscale; Msh[3][tid] = m.w*mscale;
    }
    #pragma unroll
    for (int rr = 0; rr < 2; rr++){
        int h = hh + 160*rr;
        float4 v = *(const float4*)&d_scr[(long)(g*NN + h)*NN + cw0 + 2*e];
        SA[(2*e)*LSZ + h]   = make_float2(v.x, v.y);
        SA[(2*e+1)*LSZ + h] = make_float2(v.z, v.w);
    }
    __syncthreads();
    if (tid < 160){
        int fi = tid / 40, p = tid % 40;
        float2* A = SA + fi*LSZ;
        float2* B = SB + fi*LSZ;
        float2 v[8];
        #pragma unroll
        for (int j = 0; j < 8; j++) v[j] = A[p + 40*j];
        r8f(v);
        float2 w[8]; twchain7(Wsh[p], w);
        B[PAD(8*p)] = v[0];
        #pragma unroll
        for (int r = 1; r < 8; r++) B[PAD(8*p + r)] = cml(v[r], w[r]);
    }
    __syncthreads();
    if (tid < 160){
        int fi = tid / 40, u = tid % 40, q = u & 7, p = u >> 3;
        float2* A = SA + fi*LSZ;
        float2* B = SB + fi*LSZ;
        float2 v[8];
        #pragma unroll
        for (int j = 0; j < 8; j++) v[j] = B[PAD(q + 8*p + 40*j)];
        r8f(v);
        float2 w[8]; twchain7(Wsh[8*p], w);
        A[PAD(q + 64*p)] = v[0];
        #pragma unroll
        for (int r = 1; r < 8; r++) A[PAD(q + 64*p + 8*r)] = cml(v[r], w[r]);
    }
    __syncthreads();
    if (tid < 256){
        int fi = tid >> 6, q = tid & 63;
        float2* A = SA + fi*LSZ;
        float2 x[5];
        #pragma unroll
        for (int j = 0; j < 5; j++) x[j] = A[PAD(q + 64*j)];
        r5b<1>(x);
        #pragma unroll
        for (int j = 0; j < 5; j++){
            float m = Msh[fi][q + 64*j];
            x[j] = make_float2(x[j].x*m, x[j].y*m);
        }
        r5b<-1>(x);
        #pragma unroll
        for (int j = 0; j < 5; j++) A[PAD(q + 64*j)] = x[j];
    }
    __syncthreads();
    if (tid < 160){
        int fi = tid / 40, u = tid % 40, q = u & 7, p = u >> 3;
        float2* A = SA + fi*LSZ;
        float2* B = SB + fi*LSZ;
        float2 w[8]; twchain7(cj(Wsh[8*p]), w);
        float2 v[8];
        v[0] = A[PAD(q + 64*p)];
        #pragma unroll
        for (int r = 1; r < 8; r++) v[r] = cml(A[PAD(q + 64*p + 8*r)], w[r]);
        r8i(v);
        #pragma unroll
        for (int j = 0; j < 8; j++) B[PAD(q + 8*p + 40*j)] = v[j];
    }
    __syncthreads();
    if (tid < 160){
        int fi = tid / 40, p = tid % 40;
        float2* A = SA + fi*LSZ;
        float2* B = SB + fi*LSZ;
        float2 w[8]; twchain7(cj(Wsh[p]), w);
        float2 v[8];
        v[0] = B[PAD(8*p)];
        #pragma unroll
        for (int r = 1; r < 8; r++) v[r] = cml(B[PAD(8*p + r)], w[r]);
        r8i(v);
        #pragma unroll
        for (int j = 0; j < 8; j++) A[p + 40*j] = v[j];
    }
    __syncthreads();
    #pragma unroll
    for (int rr = 0; rr < 2; rr++){
        int h = hh + 160*rr;
        float2 v0 = SA[(2*e)*LSZ + h], v1 = SA[(2*e+1)*LSZ + h];
        *(float4*)&d_scr[(long)(g*NN + h)*NN + cw0 + 2*e] = make_float4(v0.x, v0.y, v1.x, v1.y);
    }
}

// ---------------- K2b: RHS column inverse FFT of mask*kdata (legacy, one-time) ----------------
__global__ void __launch_bounds__(320) k_col_rhs(const float2* __restrict__ kd,
                                                 const float* __restrict__ mask, float mscale){
    __shared__ float2 Ash[4][321], Bsh[4][321], Wsh[NN];
    int tid = threadIdx.x, lane = tid / 80, u = tid % 80;
    Wsh[tid] = d_W[tid];
    int bid = blockIdx.x;
    int g = bid / 80;
    int cw0 = (bid % 80) * 4;
    int s = g >> 4;
    int e = tid & 1, hh = tid >> 1;
    #pragma unroll
    for (int rr = 0; rr < 2; rr++){
        int j = hh + 160*rr;
        int hr = rot160(j);
        const float4* k4 = (const float4*)&kd[(long)(g*NN + hr)*NN + cw0 + 2*e];
        float4 v = k4[0];
        float m0 = mask[(s*NN + hr)*NN + cw0 + 2*e    ] * mscale;
        float m1 = mask[(s*NN + hr)*NN + cw0 + 2*e + 1] * mscale;
        Ash[2*e  ][j] = make_float2(v.x*m0, v.y*m0);
        Ash[2*e+1][j] = make_float2(v.z*m1, v.w*m1);
    }
    __syncthreads();
    fft320<-1>(Ash[lane], Bsh[lane], Wsh, u);
    #pragma unroll
    for (int rr = 0; rr < 2; rr++){
        int h = hh + 160*rr;
        float4* s4 = (float4*)&d_scr[(long)(g*NN + h)*NN + cw0 + 2*e];
        float2 v0 = Ash[2*e][h], v1 = Ash[2*e+1][h];
        s4[0] = make_float4(v0.x, v0.y, v1.x, v1.y);
    }
}

// ---------------- K3: row inverse FFT [5,8,8] mirror + coil combine in regs ----------------
__global__ void __launch_bounds__(320, 4) k_inv_row(const float2* __restrict__ csm,
                                                    const float2* __restrict__ z,
                                                    float2* __restrict__ out,
                                                    float* __restrict__ part,
                                                    int dotMode, int initMode){
    __shared__ float2 SA[4*LSZ], SB[4*LSZ], Wsh[NN];
    int tid = threadIdx.x;
    Wsh[tid] = d_W[tid];
    int bid = blockIdx.x;
    int s  = bid / NN;
    int hp = bid % NN;
    int hf = rot160(hp);
    float2 acc[8];
    #pragma unroll
    for (int j = 0; j < 8; j++) acc[j] = make_float2(0.f, 0.f);
    for (int it = 0; it < 4; ++it){
        __syncthreads();   // prev iS1 reads done; Wsh ready on it=0
        // iS3: radix-5 inverse straight from global (freq layout, rot folded)
        if (tid < 256){
            int fi = tid >> 6, q = tid & 63;
            int g = s*16 + 4*it + fi;
            long base = (long)(g*NN + hp)*NN;
            float2 x[5];
            #pragma unroll
            for (int j = 0; j < 5; j++){
                int f = q + 64*j;
                x[j] = d_scr[base + (f < HN ? f + HN : f - HN)];
            }
            r5b<-1>(x);
            float2* A = SA + fi*LSZ;
            #pragma unroll
            for (int j = 0; j < 5; j++) A[PAD(q + 64*j)] = x[j];
        }
        __syncthreads();
        // iS2
        if (tid < 160){
            int fi = tid / 40, u = tid % 40, q = u & 7, p = u >> 3;
            float2* A = SA + fi*LSZ;
            float2* B = SB + fi*LSZ;
            float2 w[8]; twchain7(cj(Wsh[8*p]), w);
            float2 v[8];
            v[0] = A[PAD(q + 64*p)];
            #pragma unroll
            for (int r = 1; r < 8; r++) v[r] = cml(A[PAD(q + 64*p + 8*r)], w[r]);
            r8i(v);
            #pragma unroll
            for (int j = 0; j < 8; j++) B[PAD(q + 8*p + 40*j)] = v[j];
        }
        __syncthreads();
        // iS1 + conj(csm) accumulate in registers
        if (tid < 160){
            int fi = tid / 40, p = tid % 40;
            int c = 4*it + fi;
            float2* B = SB + fi*LSZ;
            float2 w[8]; twchain7(cj(Wsh[p]), w);
            float2 v[8];
            v[0] = B[PAD(8*p)];
            #pragma unroll
            for (int r = 1; r < 8; r++) v[r] = cml(B[PAD(8*p + r)], w[r]);
            r8i(v);
            long cb = (long)(c*NN + hf)*NN;
            #pragma unroll
            for (int j = 0; j < 8; j++){
                int wpos = p + 40*((j + 4) & 7);     // fftshift fold
                acc[j] = cad(acc[j], cmlcj(v[j], csm[cb + wpos]));
            }
        }
    }
    // combine 4 coil-lanes
    __syncthreads();
    if (tid < 160){
        int fi = tid / 40, p = tid % 40;
        float2* B = SB + fi*LSZ;
        #pragma unroll
        for (int j = 0; j < 8; j++) B[p + 40*((j + 4) & 7)] = acc[j];
    }
    __syncthreads();
    float2 tot = make_float2(0.f, 0.f);
    #pragma unroll
    for (int l = 0; l < 4; l++) tot = cad(tot, SB[l*LSZ + tid]);
    int oi = (s*NN + hf)*NN + tid;
    float2 zv = z[oi];
    float2 o  = make_float2(fmaf(RHO_F, zv.x, tot.x), fmaf(RHO_F, zv.y, tot.y));
    out[oi] = o;
    if (initMode){
        d_p[oi] = o;
        d_x[oi] = make_float2(0.f, 0.f);
    }
    float dv = dotMode ? (o.x*o.x + o.y*o.y) : (zv.x*o.x + zv.y*o.y);
    reduce320(dv, part);
}

// ---------------- CG updates ----------------
__global__ void __launch_bounds__(1024) k_axpy(const float* __restrict__ partP,
                                               const float* __restrict__ prCur, int nCur,
                                               float* __restrict__ prNxt,
                                               float2* __restrict__ outp, int last){
    float rs  = bsum1024(prCur, nCur);
    float pAp = bsum1024(partP, 1280);
    float alpha = rs / (pAp + EPS_F);
    int i = blockIdx.x*1024 + threadIdx.x;
    float2 pv = d_p[i], xv = d_x[i];
    xv.x = fmaf(alpha, pv.x, xv.x); xv.y = fmaf(alpha, pv.y, xv.y);
    if (last){ outp[i] = xv; return; }
    d_x[i] = xv;
    float2 av = d_Ap[i], rv = d_r[i];
    rv.x = fmaf(-alpha, av.x, rv.x); rv.y = fmaf(-alpha, av.y, rv.y);
    d_r[i] = rv;
    float dv = rv.x*rv.x + rv.y*rv.y;
    __shared__ float rb[32];
    int tid = threadIdx.x;
    #pragma unroll
    for (int o = 16; o > 0; o >>= 1) dv += __shfl_down_sync(0xffffffffu, dv, o);
    if ((tid & 31) == 0) rb[tid >> 5] = dv;
    __syncthreads();
    if (tid == 0){
        float t = 0.f;
        #pragma unroll
        for (int k = 0; k < 32; k++) t += rb[k];
        prNxt[blockIdx.x] = t;
    }
}
__global__ void __launch_bounds__(1024) k_updp(const float* __restrict__ prCur, int nCur,
                                               const float* __restrict__ prNxt){
    float rsn = bsum1024(prNxt, 400);
    float rso = bsum1024(prCur, nCur);
    float beta = rsn / (rso + EPS_F);
    int i = blockIdx.x*1024 + threadIdx.x;
    float2 rv = d_r[i], pv = d_p[i];
    d_p[i] = make_float2(fmaf(beta, pv.x, rv.x), fmaf(beta, pv.y, rv.y));
}

// ---------------- launch ----------------
extern "C" void kernel_launch(void* const* d_in, const int* in_sizes, int n_in,
                              void* d_out, int out_size){
    const float2* kd = nullptr; const float2* I = nullptr;
    const float2* csm = nullptr; const float* mask = nullptr;
    for (int i = 0; i < n_in; i++){
        int sz = in_sizes[i];
        if      (sz == 13107200) kd   = (const float2*)d_in[i];
        else if (sz == 819200)   I    = (const float2*)d_in[i];
        else if (sz == 3276800)  csm  = (const float2*)d_in[i];
        else if (sz == 409600)   mask = (const float*) d_in[i];
    }
    float2 *rp, *pp, *App; float *partP, *pr0, *pr1;
    cudaGetSymbolAddress((void**)&rp,    d_r);
    cudaGetSymbolAddress((void**)&pp,    d_p);
    cudaGetSymbolAddress((void**)&App,   d_Ap);
    cudaGetSymbolAddress((void**)&partP, d_partP);
    cudaGetSymbolAddress((void**)&pr0,   d_pr0);
    cudaGetSymbolAddress((void**)&pr1,   d_pr1);

    const float invN  = 1.0f / 320.0f;
    const float invN2 = 1.0f / (320.0f * 320.0f);

    k_init_tw<<<1, 320>>>();
    k_col_rhs<<<5120, 320>>>(kd, mask, invN);
    k_inv_row<<<1280, 320>>>(csm, I, rp, pr0, 1, 1);

    for (int it = 0; it < 15; ++it){
        int last = (it == 14);
        float* cur = (it & 1) ? pr1 : pr0;
        float* nxt = (it & 1) ? pr0 : pr1;
        int nCur = (it == 0) ? 1280 : 400;

        k_fwd_row<<<5120, 320>>>(csm, pp);
        k_col_ata<<<5120, 320>>>(mask, invN2);
        k_inv_row<<<1280, 320>>>(csm, pp, App, partP, 0, 0);
        k_axpy<<<400, 1024>>>(partP, cur, nCur, nxt, (float2*)d_out, last);
        if (!last)
            k_updp<<<400, 1024>>>(cur, nCur, nxt);
    }
    (void)out_size;
}